// round 1
// baseline (speedup 1.0000x reference)
#include <cuda_runtime.h>

#define T_MAX   1024
#define BATCH   1024
#define NS      64
#define WPB     4          // warps (=batches) per block
#define BSTRIDE (BATCH * NS)

// ---- packed f32x2 helpers (sm_103a) ----
__device__ __forceinline__ unsigned long long ffma2(unsigned long long a,
                                                    unsigned long long b,
                                                    unsigned long long c) {
    unsigned long long d;
    asm("fma.rn.f32x2 %0, %1, %2, %3;" : "=l"(d) : "l"(a), "l"(b), "l"(c));
    return d;
}
__device__ __forceinline__ unsigned long long fadd2(unsigned long long a,
                                                    unsigned long long b) {
    unsigned long long d;
    asm("add.rn.f32x2 %0, %1, %2;" : "=l"(d) : "l"(a), "l"(b));
    return d;
}
__device__ __forceinline__ unsigned long long pack2(float lo, float hi) {
    unsigned long long d;
    asm("mov.b64 %0, {%1, %2};" : "=l"(d)
        : "r"(__float_as_uint(lo)), "r"(__float_as_uint(hi)));
    return d;
}
__device__ __forceinline__ float lo32(unsigned long long v) {
    return __uint_as_float((unsigned)(v & 0xffffffffull));
}
__device__ __forceinline__ float hi32(unsigned long long v) {
    return __uint_as_float((unsigned)(v >> 32));
}

__global__ void __launch_bounds__(WPB * 32)
crf_forward_kernel(const float* __restrict__ em,
                   const int*   __restrict__ seq,
                   const float* __restrict__ start,
                   const float* __restrict__ stop,
                   const float* __restrict__ trans,
                   float*       __restrict__ out)
{
    __shared__ __align__(16) float a_buf[WPB][NS];

    const int w    = threadIdx.x >> 5;
    const int lane = threadIdx.x & 31;
    const int b    = blockIdx.x * WPB + w;
    const int s0   = lane;
    const int s1   = lane + 32;

    // ---- one-time: exp(transition) rows for my two output states, in regs ----
    unsigned long long E0[32], E1[32];
    {
        const float4* tr0 = (const float4*)(trans + s0 * NS);
        const float4* tr1 = (const float4*)(trans + s1 * NS);
#pragma unroll
        for (int j = 0; j < 16; j++) {
            float4 r0 = __ldg(tr0 + j);
            float4 r1 = __ldg(tr1 + j);
            E0[2 * j]     = pack2(__expf(r0.x), __expf(r0.y));
            E0[2 * j + 1] = pack2(__expf(r0.z), __expf(r0.w));
            E1[2 * j]     = pack2(__expf(r1.x), __expf(r1.y));
            E1[2 * j + 1] = pack2(__expf(r1.z), __expf(r1.w));
        }
    }

    const int   L   = seq[b];
    const float* emb = em + (size_t)b * NS;

    // ---- init: a = exp(start + em_0), C = 0 ----
    float cur0 = __expf(__ldg(start + s0) + __ldg(emb + s0));
    float cur1 = __expf(__ldg(start + s1) + __ldg(emb + s1));
    a_buf[w][s0] = cur0;
    a_buf[w][s1] = cur1;
    float C = 0.0f;
    const float estop0 = __expf(__ldg(stop + s0));
    const float estop1 = __expf(__ldg(stop + s1));
    __syncwarp();

    // ---- 4-deep emission prefetch ring ----
    float rA[4], rB[4];
#pragma unroll
    for (int i = 0; i < 4; i++) {
        int tt = 1 + i;
        bool v = tt < L;
        rA[i] = v ? __ldg(emb + (size_t)tt * BSTRIDE + s0) : 0.0f;
        rB[i] = v ? __ldg(emb + (size_t)tt * BSTRIDE + s1) : 0.0f;
    }

#define CRF_BODY(emA_, emB_)                                                   \
    do {                                                                       \
        unsigned long long acc00 = 0ull, acc01 = 0ull;                         \
        unsigned long long acc10 = 0ull, acc11 = 0ull;                         \
        const ulonglong2* a2 = (const ulonglong2*)a_buf[w];                    \
        _Pragma("unroll")                                                      \
        for (int j = 0; j < 16; j++) {                                         \
            ulonglong2 av = a2[j];                                             \
            acc00 = ffma2(av.x, E0[2 * j],     acc00);                         \
            acc01 = ffma2(av.y, E0[2 * j + 1], acc01);                         \
            acc10 = ffma2(av.x, E1[2 * j],     acc10);                         \
            acc11 = ffma2(av.y, E1[2 * j + 1], acc11);                         \
        }                                                                      \
        unsigned long long va = fadd2(acc00, acc01);                           \
        unsigned long long vb = fadd2(acc10, acc11);                           \
        float v0 = lo32(va) + hi32(va);                                        \
        float v1 = lo32(vb) + hi32(vb);                                        \
        float vref = __shfl_sync(0xffffffffu, v0, 0);                          \
        float rv = __fdividef(1.0f, vref);                                     \
        C += __logf(vref);                                                     \
        cur0 = v0 * rv * __expf(emA_);                                         \
        cur1 = v1 * rv * __expf(emB_);                                         \
        __syncwarp();                                                          \
        a_buf[w][s0] = cur0;                                                   \
        a_buf[w][s1] = cur1;                                                   \
        __syncwarp();                                                          \
    } while (0)

#define CRF_STEP(tcur_, slot_)                                                 \
    do {                                                                       \
        float emA = rA[slot_];                                                 \
        float emB = rB[slot_];                                                 \
        int tp = (tcur_) + 4;                                                  \
        if (tp < L) {                                                          \
            rA[slot_] = __ldg(emb + (size_t)tp * BSTRIDE + s0);                \
            rB[slot_] = __ldg(emb + (size_t)tp * BSTRIDE + s1);                \
        }                                                                      \
        CRF_BODY(emA, emB);                                                    \
    } while (0)

    int t = 1;
    for (; t + 3 < L; t += 4) {
        CRF_STEP(t,     0);
        CRF_STEP(t + 1, 1);
        CRF_STEP(t + 2, 2);
        CRF_STEP(t + 3, 3);
    }
    // tail: remaining steps use ring slots 0,1,2 in order (t ≡ 1 mod 4 here)
    if (t < L) { CRF_BODY(rA[0], rB[0]); t++; }
    if (t < L) { CRF_BODY(rA[1], rB[1]); t++; }
    if (t < L) { CRF_BODY(rA[2], rB[2]); }

    // ---- finalize: logZ = log(sum_s a[s]*exp(stop[s])) + C ----
    float z = cur0 * estop0 + cur1 * estop1;
#pragma unroll
    for (int o = 16; o; o >>= 1)
        z += __shfl_xor_sync(0xffffffffu, z, o);
    if (lane == 0)
        out[b] = __logf(z) + C;
}

extern "C" void kernel_launch(void* const* d_in, const int* in_sizes, int n_in,
                              void* d_out, int out_size)
{
    const float* em    = (const float*)d_in[0];
    const int*   seq   = (const int*)d_in[1];
    const float* start = (const float*)d_in[2];
    const float* stop  = (const float*)d_in[3];
    const float* trans = (const float*)d_in[4];
    float*       out   = (float*)d_out;

    crf_forward_kernel<<<BATCH / WPB, WPB * 32>>>(em, seq, start, stop, trans, out);
}